// round 11
// baseline (speedup 1.0000x reference)
#include <cuda_runtime.h>
#include <cuda_fp16.h>
#include <mma.h>
#include <cstdint>

using namespace nvcuda;

#define BN     50000
#define NBR    4
#define DD     32
#define CC     128          // NBR*DD
#define MM     256
#define NODES  (BN + MM)    // 50256
#define CAPR   128          // per-batch-row bucket capacity (mean ~40)
#define HROWS  64           // rows per compute_h block
#define XPAD   132          // padded row stride (floats)
#define YROWS  64           // rows per y block

// scratch (static device globals — no allocation)
__device__ __half g_h16[(size_t)NODES * CC];   // 12.9MB (Y path only)
__device__ __half g_out16[(size_t)BN * CC];    // gather result, fp16 (y input)
__device__ __half g_wfc16[CC * CC];            // W_fc in fp16
__device__ int    g_cnt[BN];
__device__ int2   g_ent[(size_t)BN * CAPR];    // (src_row, w_bits) per batch-dst
__device__ float  g_vq32[MM * CC];             // vq_grad re-laid [m][b*32+e], 128KB
__device__ float  g_vsum[(size_t)BN * CC];     // per-row sum w*vq (fp32)
__device__ float  g_info;

// ---------------------------------------------------------------------------
// prep: zero counters/info + relayout vq_grad + convert W_fc to fp16
// ---------------------------------------------------------------------------
__global__ void prep_kernel(const float* __restrict__ vq_grad,
                            const float* __restrict__ W_fc) {
    const int idx = blockIdx.x * blockDim.x + threadIdx.x;
    if (idx < NBR * MM * DD) {
        const int b = idx >> 13;
        const int m = (idx >> 5) & (MM - 1);
        const int e = idx & 31;
        g_vq32[m * CC + b * DD + e] = vq_grad[idx];
    }
    if (idx < CC * CC) g_wfc16[idx] = __float2half_rn(W_fc[idx]);
    if (idx < BN) g_cnt[idx] = 0;
    if (idx == 0) g_info = 0.0f;
}

// ---------------------------------------------------------------------------
// Bucket all edges by destination batch row (1 edge per thread).
// ---------------------------------------------------------------------------
__global__ void fill_dst_kernel(const int* __restrict__ sbb, const int* __restrict__ dbb,
                                const float* __restrict__ wbb,
                                const int* __restrict__ sbm, const int* __restrict__ dbm,
                                const float* __restrict__ wbm,
                                const int* __restrict__ cidx, int Ebb, int Etot) {
    const int i = blockIdx.x * blockDim.x + threadIdx.x;
    if (i >= Etot) return;
    int r, s; float w;
    if (i < Ebb) { r = dbb[i]; s = sbb[i]; w = wbb[i]; }
    else { const int j = i - Ebb; r = dbm[j]; s = BN + cidx[sbm[j]]; w = wbm[j]; }
    const int pos = atomicAdd(&g_cnt[r], 1);
    if (pos < CAPR)
        g_ent[(size_t)r * CAPR + pos] = make_int2(s, __float_as_int(w));
}

// ---------------------------------------------------------------------------
// vsum[r] = sum over bucket entries with src >= BN of w * vq32[src-BN].
// Warp-uniform branch skips bb entries; 4-wide entry lookahead.
// Entry stream uses __ldcs so the L1-resident vq32 (128KB) stays hot.
// ---------------------------------------------------------------------------
__device__ __forceinline__ void vs_proc(float4& vs, int2 E, int lane) {
    if (E.x >= BN) {                     // warp-uniform branch
        const float w = __int_as_float(E.y);
        const float4 qv = ((const float4*)(g_vq32 + (size_t)(E.x - BN) * CC))[lane];
        vs.x = fmaf(w, qv.x, vs.x); vs.y = fmaf(w, qv.y, vs.y);
        vs.z = fmaf(w, qv.z, vs.z); vs.w = fmaf(w, qv.w, vs.w);
    }
}

__global__ void vsum_kernel() {
    const int gw   = (blockIdx.x * blockDim.x + threadIdx.x) >> 5;
    const int lane = threadIdx.x & 31;
    if (gw >= BN) return;
    int n = g_cnt[gw]; if (n > CAPR) n = CAPR;

    const int2* ep = g_ent + (size_t)gw * CAPR;
    const int2 Z = make_int2(0, 0);     // src 0 < BN -> skipped
    float4 vs = make_float4(0.f, 0.f, 0.f, 0.f);

    int2 c0 = (0 < n) ? __ldcs(ep + 0) : Z;
    int2 c1 = (1 < n) ? __ldcs(ep + 1) : Z;
    int2 c2 = (2 < n) ? __ldcs(ep + 2) : Z;
    int2 c3 = (3 < n) ? __ldcs(ep + 3) : Z;
    for (int e = 0; e < n; e += 4) {
        const int2 n0 = (e + 4 < n) ? __ldcs(ep + e + 4) : Z;
        const int2 n1 = (e + 5 < n) ? __ldcs(ep + e + 5) : Z;
        const int2 n2 = (e + 6 < n) ? __ldcs(ep + e + 6) : Z;
        const int2 n3 = (e + 7 < n) ? __ldcs(ep + e + 7) : Z;
        vs_proc(vs, c0, lane); vs_proc(vs, c1, lane);
        vs_proc(vs, c2, lane); vs_proc(vs, c3, lane);
        c0 = n0; c1 = n1; c2 = n2; c3 = n3;
    }
    ((float4*)(g_vsum + (size_t)gw * CC))[lane] = vs;
}

// ---------------------------------------------------------------------------
// compute_h v3: register-tiled GEMM (round-9, known-good).
// ---------------------------------------------------------------------------
__global__ void compute_h_kernel(const float* __restrict__ X,
                                 const float* __restrict__ codebook,
                                 const float* __restrict__ W_conv,
                                 const float* __restrict__ wr_p) {
    __shared__ float Ws[NBR * DD * DD];   // 16KB, [b][d][e]
    __shared__ float Xs[HROWS][XPAD];     // 33KB padded
    __shared__ float wred[8];

    for (int i = threadIdx.x; i < NBR * DD * DD; i += blockDim.x)
        Ws[i] = W_conv[i];

    const int row0 = blockIdx.x * HROWS;
    const float wr = wr_p[0];

    for (int i = threadIdx.x; i < HROWS * 32; i += 256) {
        const int r  = i >> 5;
        const int c4 = i & 31;
        const int row = row0 + r;
        float4 v = make_float4(0.f, 0.f, 0.f, 0.f);
        if (row < BN) {
            v = ((const float4*)X)[(size_t)row * 32 + c4];
        } else if (row < NODES) {
            const int b = c4 >> 3, sub = c4 & 7, m = row - BN;
            v = ((const float4*)codebook)[((size_t)b * MM + m) * 8 + sub];
            v.x *= wr; v.y *= wr; v.z *= wr; v.w *= wr;
        }
        *(float4*)&Xs[r][c4 * 4] = v;
    }
    __syncthreads();

    const int wid  = threadIdx.x >> 5;
    const int lane = threadIdx.x & 31;
    const int rgrp = wid >> 2;
    const int b    = wid & 3;
    const int rg   = lane >> 2;
    const int cg   = lane & 3;

    float acc[4][8];
    #pragma unroll
    for (int rr = 0; rr < 4; rr++)
        #pragma unroll
        for (int c = 0; c < 8; c++) acc[rr][c] = 0.0f;

    const float* wbp = &Ws[b * (DD * DD) + cg * 8];
    const int lrow0 = rgrp * 32 + rg;

    #pragma unroll
    for (int d = 0; d < DD; d++) {
        const float4 wv0 = *(const float4*)(wbp + d * DD);
        const float4 wv1 = *(const float4*)(wbp + d * DD + 4);
        #pragma unroll
        for (int rr = 0; rr < 4; rr++) {
            const float xv = Xs[lrow0 + 8 * rr][b * DD + d];
            acc[rr][0] = fmaf(xv, wv0.x, acc[rr][0]);
            acc[rr][1] = fmaf(xv, wv0.y, acc[rr][1]);
            acc[rr][2] = fmaf(xv, wv0.z, acc[rr][2]);
            acc[rr][3] = fmaf(xv, wv0.w, acc[rr][3]);
            acc[rr][4] = fmaf(xv, wv1.x, acc[rr][4]);
            acc[rr][5] = fmaf(xv, wv1.y, acc[rr][5]);
            acc[rr][6] = fmaf(xv, wv1.z, acc[rr][6]);
            acc[rr][7] = fmaf(xv, wv1.w, acc[rr][7]);
        }
    }

    float p = 0.0f;
    #pragma unroll
    for (int rr = 0; rr < 4; rr++) {
        const int row = row0 + lrow0 + 8 * rr;
        if (row < BN) {
            const float4* vp = (const float4*)(g_vsum + (size_t)row * CC + b * DD + cg * 8);
            const float4 v0 = vp[0];
            const float4 v1 = vp[1];
            p = fmaf(acc[rr][0], v0.x, p); p = fmaf(acc[rr][1], v0.y, p);
            p = fmaf(acc[rr][2], v0.z, p); p = fmaf(acc[rr][3], v0.w, p);
            p = fmaf(acc[rr][4], v1.x, p); p = fmaf(acc[rr][5], v1.y, p);
            p = fmaf(acc[rr][6], v1.z, p); p = fmaf(acc[rr][7], v1.w, p);
        }
        if (row < NODES) {
            __half2 h0 = __floats2half2_rn(acc[rr][0], acc[rr][1]);
            __half2 h1 = __floats2half2_rn(acc[rr][2], acc[rr][3]);
            __half2 h2 = __floats2half2_rn(acc[rr][4], acc[rr][5]);
            __half2 h3 = __floats2half2_rn(acc[rr][6], acc[rr][7]);
            uint4 pk;
            pk.x = *(unsigned*)&h0; pk.y = *(unsigned*)&h1;
            pk.z = *(unsigned*)&h2; pk.w = *(unsigned*)&h3;
            *(uint4*)(g_h16 + (size_t)row * CC + b * DD + cg * 8) = pk;
        }
    }

    #pragma unroll
    for (int s = 16; s > 0; s >>= 1)
        p += __shfl_xor_sync(0xFFFFFFFF, p, s);
    if (lane == 0) wred[wid] = p;
    __syncthreads();
    if (threadIdx.x == 0) {
        float s = wred[0] + wred[1] + wred[2] + wred[3]
                + wred[4] + wred[5] + wred[6] + wred[7];
        if (s != 0.0f) atomicAdd(&g_info, s);
    }
}

// ---------------------------------------------------------------------------
// Gather: one warp per batch row. out16[r] = fp16(b_conv + sum w * h16[src]).
// Cache-policy split (warp-uniform branch):
//   codeword src rows (>=BN, 64KB total) -> default load, stay L1-resident
//   batch src rows (12.9MB stream)       -> __ldcs, evict-first
//   bucket entries                       -> __ldcs
// 4-wide batched h loads for MLP.
// ---------------------------------------------------------------------------
__device__ __forceinline__ uint2 load_h(int2 E, int lane) {
    const uint2* hp = (const uint2*)(g_h16 + (size_t)E.x * CC) + lane;
    if (E.x >= BN) return *hp;          // L1-cached (codeword rows hot)
    return __ldcs(hp);                  // streaming (don't pollute L1)
}

__device__ __forceinline__ void fma_h16(float4& acc, int2 ent, uint2 hv) {
    const float w = __int_as_float(ent.y);
    const float2 f0 = __half22float2(*(const __half2*)&hv.x);
    const float2 f1 = __half22float2(*(const __half2*)&hv.y);
    acc.x = fmaf(w, f0.x, acc.x); acc.y = fmaf(w, f0.y, acc.y);
    acc.z = fmaf(w, f1.x, acc.z); acc.w = fmaf(w, f1.y, acc.w);
}

__global__ void gather_kernel(const float* __restrict__ b_conv) {
    const int gw   = (blockIdx.x * blockDim.x + threadIdx.x) >> 5;
    const int lane = threadIdx.x & 31;
    if (gw >= BN) return;
    int n = g_cnt[gw]; if (n > CAPR) n = CAPR;

    float4 acc = ((const float4*)b_conv)[lane];
    const int2* ep = g_ent + (size_t)gw * CAPR;
    const int2 Z = make_int2(0, 0);   // src row 0, w == 0.0f

    int2 E0 = (0 < n) ? __ldcs(ep + 0) : Z;
    int2 E1 = (1 < n) ? __ldcs(ep + 1) : Z;
    int2 E2 = (2 < n) ? __ldcs(ep + 2) : Z;
    int2 E3 = (3 < n) ? __ldcs(ep + 3) : Z;

    for (int e = 0; e < n; e += 4) {
        const int2 N0 = (e + 4 < n) ? __ldcs(ep + e + 4) : Z;
        const int2 N1 = (e + 5 < n) ? __ldcs(ep + e + 5) : Z;
        const int2 N2 = (e + 6 < n) ? __ldcs(ep + e + 6) : Z;
        const int2 N3 = (e + 7 < n) ? __ldcs(ep + e + 7) : Z;
        const uint2 h0 = load_h(E0, lane);
        const uint2 h1 = load_h(E1, lane);
        const uint2 h2 = load_h(E2, lane);
        const uint2 h3 = load_h(E3, lane);
        fma_h16(acc, E0, h0); fma_h16(acc, E1, h1);
        fma_h16(acc, E2, h2); fma_h16(acc, E3, h3);
        E0 = N0; E1 = N1; E2 = N2; E3 = N3;
    }

    __half2 o0 = __floats2half2_rn(acc.x, acc.y);
    __half2 o1 = __floats2half2_rn(acc.z, acc.w);
    uint2 pk;
    pk.x = *(unsigned*)&o0;
    pk.y = *(unsigned*)&o1;
    ((uint2*)(g_out16 + (size_t)gw * CC))[lane] = pk;
}

// ---------------------------------------------------------------------------
// finalize: out_scalar = (g_info + sum b_conv[col]*vq[b,m,e]) * wr
// ---------------------------------------------------------------------------
__global__ void finalize_kernel(const float* __restrict__ vq_grad,
                                const float* __restrict__ b_conv,
                                const float* __restrict__ wr_p,
                                float* __restrict__ out_scalar) {
    __shared__ float red[256];
    float s = 0.0f;
    for (int idx = threadIdx.x; idx < NBR * MM * DD; idx += 256) {
        const int b = idx >> 13;
        const int e = idx & 31;
        s += b_conv[b * DD + e] * vq_grad[idx];
    }
    red[threadIdx.x] = s;
    __syncthreads();
    for (int st = 128; st > 0; st >>= 1) {
        if (threadIdx.x < st) red[threadIdx.x] += red[threadIdx.x + st];
        __syncthreads();
    }
    if (threadIdx.x == 0) *out_scalar = (red[0] + g_info) * wr_p[0];
}

// ---------------------------------------------------------------------------
// y_kernel (WMMA): Y[r,c] = (out16 @ W16)[r,c] + b_fc[c] + X_B[r,c]
// ---------------------------------------------------------------------------
__global__ void y_kernel(const float* __restrict__ X,
                         const float* __restrict__ b_fc,
                         float* __restrict__ Y) {
    __shared__ __align__(16) char sraw[49152];
    __half* As = (__half*)sraw;                   // [64][128]
    __half* Bs = (__half*)(sraw + 16384);         // [128][128]
    float*  Ob = (float*)sraw;                    // [64][128] (after loop)

    const int row0 = blockIdx.x * YROWS;
    const int tid  = threadIdx.x;

    for (int i = tid; i < 1024; i += 256) {
        const int r = i >> 4, c16 = i & 15;
        const int row = row0 + r;
        uint4 v = make_uint4(0, 0, 0, 0);
        if (row < BN) v = ((const uint4*)(g_out16 + (size_t)row * CC))[c16];
        ((uint4*)As)[i] = v;
    }
    for (int i = tid; i < 2048; i += 256)
        ((uint4*)Bs)[i] = ((const uint4*)g_wfc16)[i];
    __syncthreads();

    const int w  = tid >> 5;
    const int rt = w >> 1;          // 0..3
    const int ch = w & 1;           // 0/1

    wmma::fragment<wmma::accumulator, 16, 16, 16, float> accf[4];
    #pragma unroll
    for (int t = 0; t < 4; t++) wmma::fill_fragment(accf[t], 0.0f);

    #pragma unroll
    for (int k = 0; k < 8; k++) {
        wmma::fragment<wmma::matrix_a, 16, 16, 16, __half, wmma::row_major> af;
        wmma::load_matrix_sync(af, As + (rt * 16) * CC + k * 16, CC);
        #pragma unroll
        for (int t = 0; t < 4; t++) {
            wmma::fragment<wmma::matrix_b, 16, 16, 16, __half, wmma::row_major> bf;
            wmma::load_matrix_sync(bf, Bs + (k * 16) * CC + ch * 64 + t * 16, CC);
            wmma::mma_sync(accf[t], af, bf, accf[t]);
        }
    }
    __syncthreads();   // done with As/Bs

    #pragma unroll
    for (int t = 0; t < 4; t++)
        wmma::store_matrix_sync(Ob + (rt * 16) * CC + ch * 64 + t * 16,
                                accf[t], CC, wmma::mem_row_major);
    __syncthreads();

    for (int i = tid; i < YROWS * 32; i += 256) {
        const int r = i >> 5, c4 = i & 31;
        const int row = row0 + r;
        if (row >= BN) continue;
        const float4 ov = ((const float4*)Ob)[r * 32 + c4];
        const float4 bv = ((const float4*)b_fc)[c4];
        const float4 xv = ((const float4*)(X + (size_t)row * CC))[c4];
        ((float4*)(Y + (size_t)row * CC))[c4] =
            make_float4(ov.x + bv.x + xv.x, ov.y + bv.y + xv.y,
                        ov.z + bv.z + xv.z, ov.w + bv.w + xv.w);
    }
}

// ---------------------------------------------------------------------------
extern "C" void kernel_launch(void* const* d_in, const int* in_sizes, int n_in,
                              void* d_out, int out_size) {
    const float* X_B      = (const float*)d_in[0];
    const int*   esrc_bb  = (const int*)  d_in[1];
    const int*   edst_bb  = (const int*)  d_in[2];
    const float* ew_bb    = (const float*)d_in[3];
    const int*   esrc_bm  = (const int*)  d_in[4];
    const int*   edst_bm  = (const int*)  d_in[5];
    const float* ew_bm    = (const float*)d_in[6];
    const int*   c_idx    = (const int*)  d_in[7];
    const float* wr       = (const float*)d_in[8];
    const float* codebook = (const float*)d_in[9];
    const float* vq_grad  = (const float*)d_in[10];
    const float* W_conv   = (const float*)d_in[11];
    const float* b_conv   = (const float*)d_in[12];
    const float* W_fc     = (const float*)d_in[13];
    const float* b_fc     = (const float*)d_in[14];
    float* out = (float*)d_out;

    const int Ebb  = in_sizes[1];
    const int Ebm  = in_sizes[4];
    const int Etot = Ebb + Ebm;

    prep_kernel<<<(BN + 255) / 256, 256>>>(vq_grad, W_fc);
    fill_dst_kernel<<<(Etot + 255) / 256, 256>>>(esrc_bb, edst_bb, ew_bb,
                                                 esrc_bm, edst_bm, ew_bm,
                                                 c_idx, Ebb, Etot);
    vsum_kernel<<<(BN * 32 + 255) / 256, 256>>>();
    compute_h_kernel<<<(NODES + HROWS - 1) / HROWS, 256>>>(X_B, codebook, W_conv, wr);
    gather_kernel<<<(BN * 32 + 255) / 256, 256>>>(b_conv);
    finalize_kernel<<<1, 256>>>(vq_grad, b_conv, wr, out + (out_size - 1));
    y_kernel<<<(BN + YROWS - 1) / YROWS, 256>>>(X_B, b_fc, out);
}